// round 2
// baseline (speedup 1.0000x reference)
#include <cuda_runtime.h>

#define NN   50000
#define HH   128
#define EE   1600000
#define EPSB 1e-5f

// -------- static device scratch (no allocation allowed) --------
__device__ int   g_row[EE];
__device__ int   g_col[EE];
__device__ int   g_src[EE];     // CSR sources
__device__ float g_wS[EE];      // CSR edge weights dinv[r]*dinv[c]
__device__ int   g_deg[NN];
__device__ float g_dinv[NN];
__device__ int   g_ptr[NN + 1];
__device__ int   g_pos[NN];
__device__ float g_xw[NN * 32];
__device__ float g_y [NN * 32];   // post-lrelu layer output
__device__ float g_x [NN * 32];   // BN-applied (final layer, FC input)
__device__ float g_ssum[3 * 32];
__device__ float g_ssq [3 * 32];
__device__ float g_bnA[32];
__device__ float g_bnB[32];
__device__ float g_fc0[128];
__device__ int   g_is64;

static __device__ __forceinline__ float lrelu(float v) {
    return v > 0.f ? v : 0.1f * v;
}

// -------- init: zero accumulators --------
__global__ void k_init() {
    int i = blockIdx.x * blockDim.x + threadIdx.x;
    if (i < NN) g_deg[i] = 0;
    if (i < 3 * 32) { g_ssum[i] = 0.f; g_ssq[i] = 0.f; }
    if (i < 128) g_fc0[i] = 0.f;
}

// -------- detect int64 vs int32 edge_index --------
__global__ void k_detect(const unsigned int* w) {
    int nz = 0;
    for (int t = 0; t < 64; t++) nz += (w[2 * t + 1] != 0u);
    g_is64 = (nz == 0) ? 1 : 0;
}

// -------- decode edges + degree histogram --------
__global__ void k_edges(const void* ei) {
    int e = blockIdx.x * blockDim.x + threadIdx.x;
    if (e >= EE) return;
    int r, c;
    if (g_is64) {
        const long long* p = (const long long*)ei;
        r = (int)p[e]; c = (int)p[EE + e];
    } else {
        const int* p = (const int*)ei;
        r = p[e]; c = p[EE + e];
    }
    g_row[e] = r; g_col[e] = c;
    atomicAdd(&g_deg[c], 1);
}

__global__ void k_dinv() {
    int i = blockIdx.x * blockDim.x + threadIdx.x;
    if (i < NN) g_dinv[i] = rsqrtf((float)g_deg[i] + 2.0f);
}

// -------- exclusive scan of degrees (single block) --------
__global__ void k_scan() {
    __shared__ int sbuf[1024];
    __shared__ int scarry;
    if (threadIdx.x == 0) scarry = 0;
    __syncthreads();
    for (int start = 0; start < NN; start += 1024) {
        int i = start + threadIdx.x;
        int v = (i < NN) ? g_deg[i] : 0;
        sbuf[threadIdx.x] = v;
        __syncthreads();
        for (int off = 1; off < 1024; off <<= 1) {
            int t = 0;
            if (threadIdx.x >= off) t = sbuf[threadIdx.x - off];
            __syncthreads();
            sbuf[threadIdx.x] += t;
            __syncthreads();
        }
        if (i < NN) {
            int excl = scarry + sbuf[threadIdx.x] - v;
            g_ptr[i] = excl;
            g_pos[i] = excl;
        }
        __syncthreads();
        if (threadIdx.x == 1023) scarry += sbuf[1023];
        __syncthreads();
    }
    if (threadIdx.x == 0) g_ptr[NN] = scarry;
}

// -------- CSR placement --------
__global__ void k_place() {
    int e = blockIdx.x * blockDim.x + threadIdx.x;
    if (e >= EE) return;
    int r = g_row[e], c = g_col[e];
    int slot = atomicAdd(&g_pos[c], 1);
    g_src[slot] = r;
    g_wS[slot] = g_dinv[r] * g_dinv[c];
}

// -------- xw = (BN(x)) @ W ; one warp per node --------
// BN=true layers read the device-global g_y directly (passing a __device__
// symbol from host code is UB — that was the R1 bug).
template<int CIN, bool BN>
__global__ __launch_bounds__(256) void k_xw(const float* __restrict__ x,
                                            const float* __restrict__ W) {
    __shared__ float sW[CIN * 32];
    for (int t = threadIdx.x; t < CIN * 32; t += 256) sW[t] = W[t];
    __syncthreads();
    int warp = threadIdx.x >> 5, lane = threadIdx.x & 31;
    int node = blockIdx.x * 8 + warp;
    if (node >= NN) return;
    const float* xr = BN ? (g_y + (size_t)node * CIN) : (x + (size_t)node * CIN);
    float acc = 0.f;
    if (CIN == 32) {
        float v = xr[lane];
        if (BN) v = v * g_bnA[lane] + g_bnB[lane];
#pragma unroll
        for (int k = 0; k < 32; k++)
            acc += __shfl_sync(0xffffffffu, v, k) * sW[k * 32 + lane];
    } else {
        float v0 = xr[lane], v1 = xr[lane + 32], v2 = xr[lane + 64], v3 = xr[lane + 96];
#pragma unroll
        for (int k = 0; k < 32; k++)
            acc += __shfl_sync(0xffffffffu, v0, k) * sW[k * 32 + lane];
#pragma unroll
        for (int k = 0; k < 32; k++)
            acc += __shfl_sync(0xffffffffu, v1, k) * sW[(k + 32) * 32 + lane];
#pragma unroll
        for (int k = 0; k < 32; k++)
            acc += __shfl_sync(0xffffffffu, v2, k) * sW[(k + 64) * 32 + lane];
#pragma unroll
        for (int k = 0; k < 32; k++)
            acc += __shfl_sync(0xffffffffu, v3, k) * sW[(k + 96) * 32 + lane];
    }
    g_xw[node * 32 + lane] = acc;
}

// -------- gather aggregation + self loop + bias + lrelu --------
__global__ __launch_bounds__(256) void k_gather(const float* __restrict__ b) {
    int tid = blockIdx.x * blockDim.x + threadIdx.x;
    int node = tid >> 3, q = tid & 7;
    if (node >= NN) return;
    const float4* xw4 = (const float4*)g_xw;
    float di = g_dinv[node];
    float sw = 2.f * di * di;
    float4 self = xw4[node * 8 + q];
    float4 acc;
    acc.x = self.x * sw + b[q * 4 + 0];
    acc.y = self.y * sw + b[q * 4 + 1];
    acc.z = self.z * sw + b[q * 4 + 2];
    acc.w = self.w * sw + b[q * 4 + 3];
    int s = g_ptr[node], e = g_ptr[node + 1];
    int i = s;
    for (; i + 1 < e; i += 2) {
        int   r0 = __ldg(&g_src[i]),   r1 = __ldg(&g_src[i + 1]);
        float w0 = __ldg(&g_wS[i]),    w1 = __ldg(&g_wS[i + 1]);
        float4 v0 = xw4[r0 * 8 + q];
        float4 v1 = xw4[r1 * 8 + q];
        acc.x += w0 * v0.x + w1 * v1.x;
        acc.y += w0 * v0.y + w1 * v1.y;
        acc.z += w0 * v0.z + w1 * v1.z;
        acc.w += w0 * v0.w + w1 * v1.w;
    }
    if (i < e) {
        int r0 = __ldg(&g_src[i]);
        float w0 = __ldg(&g_wS[i]);
        float4 v0 = xw4[r0 * 8 + q];
        acc.x += w0 * v0.x; acc.y += w0 * v0.y;
        acc.z += w0 * v0.z; acc.w += w0 * v0.w;
    }
    acc.x = lrelu(acc.x); acc.y = lrelu(acc.y);
    acc.z = lrelu(acc.z); acc.w = lrelu(acc.w);
    ((float4*)g_y)[node * 8 + q] = acc;
}

// -------- per-channel BN stats over g_y --------
__global__ __launch_bounds__(256) void k_stats(int layer) {
    int c = threadIdx.x & 31;
    int r = threadIdx.x >> 5;
    float s = 0.f, s2 = 0.f;
    for (int i = blockIdx.x * 8 + r; i < NN; i += gridDim.x * 8) {
        float v = g_y[i * 32 + c];
        s += v; s2 += v * v;
    }
    __shared__ float sh[256], sh2[256];
    sh[threadIdx.x] = s; sh2[threadIdx.x] = s2;
    __syncthreads();
    if (r == 0) {
#pragma unroll
        for (int k = 1; k < 8; k++) { s += sh[k * 32 + c]; s2 += sh2[k * 32 + c]; }
        atomicAdd(&g_ssum[layer * 32 + c], s);
        atomicAdd(&g_ssq [layer * 32 + c], s2);
    }
}

// -------- fold BN into per-channel affine --------
__global__ void k_bnp(int layer, const float* __restrict__ g, const float* __restrict__ bt) {
    int c = threadIdx.x;
    if (c >= 32) return;
    float mean = g_ssum[layer * 32 + c] / (float)NN;
    float var  = g_ssq [layer * 32 + c] / (float)NN - mean * mean;
    float a = g[c] * rsqrtf(var + EPSB);
    g_bnA[c] = a;
    g_bnB[c] = bt[c] - mean * a;
}

// -------- explicit BN apply (final layer, produces FC input) --------
__global__ void k_bnapply() {
    int i = blockIdx.x * blockDim.x + threadIdx.x;
    if (i >= NN * 32) return;
    int c = i & 31;
    g_x[i] = g_y[i] * g_bnA[c] + g_bnB[c];
}

// -------- FC0: [1, 1.6M] x [1.6M, 128] --------
__global__ __launch_bounds__(128) void k_fc0(const float* __restrict__ W0) {
    const int total = NN * 32;
    int per = ((total + gridDim.x - 1) / gridDim.x + 127) & ~127;
    int k0 = blockIdx.x * per;
    if (k0 >= total) return;
    int k1 = min(k0 + per, total);
    int j = threadIdx.x;
    __shared__ float sx[128];
    float acc = 0.f;
    for (int kb = k0; kb < k1; kb += 128) {
        int kk = kb + j;
        sx[j] = (kk < k1) ? g_x[kk] : 0.f;
        __syncthreads();
        int lim = min(128, k1 - kb);
#pragma unroll 8
        for (int t = 0; t < lim; t++)
            acc += sx[t] * W0[(size_t)(kb + t) * 128 + j];
        __syncthreads();
    }
    atomicAdd(&g_fc0[j], acc);
}

// -------- FC tail: bias+lrelu, 128->64->32->1 --------
__global__ void k_fctail(const float* __restrict__ fb0,
                         const float* __restrict__ fW1, const float* __restrict__ fb1,
                         const float* __restrict__ fW2, const float* __restrict__ fb2,
                         const float* __restrict__ fW3, const float* __restrict__ fb3,
                         float* __restrict__ out) {
    __shared__ float h1[128], h2[64], h3[32];
    int t = threadIdx.x;
    h1[t] = lrelu(g_fc0[t] + fb0[t]);
    __syncthreads();
    if (t < 64) {
        float a = fb1[t];
#pragma unroll 8
        for (int k = 0; k < 128; k++) a += h1[k] * fW1[k * 64 + t];
        h2[t] = lrelu(a);
    }
    __syncthreads();
    if (t < 32) {
        float a = fb2[t];
#pragma unroll 8
        for (int k = 0; k < 64; k++) a += h2[k] * fW2[k * 32 + t];
        h3[t] = lrelu(a);
    }
    __syncthreads();
    if (t == 0) {
        float a = fb3[0];
#pragma unroll
        for (int k = 0; k < 32; k++) a += h3[k] * fW3[k];
        out[0] = a;
    }
}

extern "C" void kernel_launch(void* const* d_in, const int* in_sizes, int n_in,
                              void* d_out, int out_size) {
    const void*  ei   = d_in[0];
    const float* emb  = (const float*)d_in[1];
    const float* cW[3] = {(const float*)d_in[2], (const float*)d_in[6], (const float*)d_in[10]};
    const float* cb[3] = {(const float*)d_in[3], (const float*)d_in[7], (const float*)d_in[11]};
    const float* gg[3] = {(const float*)d_in[4], (const float*)d_in[8], (const float*)d_in[12]};
    const float* bt[3] = {(const float*)d_in[5], (const float*)d_in[9], (const float*)d_in[13]};
    const float* fW0 = (const float*)d_in[14];
    const float* fb0 = (const float*)d_in[15];
    const float* fW1 = (const float*)d_in[16];
    const float* fb1 = (const float*)d_in[17];
    const float* fW2 = (const float*)d_in[18];
    const float* fb2 = (const float*)d_in[19];
    const float* fW3 = (const float*)d_in[20];
    const float* fb3 = (const float*)d_in[21];
    float* out = (float*)d_out;

    k_init<<<(NN + 255) / 256, 256>>>();
    k_detect<<<1, 1>>>((const unsigned int*)ei);
    k_edges<<<(EE + 255) / 256, 256>>>(ei);
    k_dinv<<<(NN + 255) / 256, 256>>>();
    k_scan<<<1, 1024>>>();
    k_place<<<(EE + 255) / 256, 256>>>();

    // layer 0 (CIN=128, no BN on input)
    k_xw<128, false><<<(NN + 7) / 8, 256>>>(emb, cW[0]);
    k_gather<<<(NN * 8 + 255) / 256, 256>>>(cb[0]);
    k_stats<<<256, 256>>>(0);
    k_bnp<<<1, 32>>>(0, gg[0], bt[0]);

    // layer 1 (CIN=32, BN folded into xw input, reads g_y device-side)
    k_xw<32, true><<<(NN + 7) / 8, 256>>>(nullptr, cW[1]);
    k_gather<<<(NN * 8 + 255) / 256, 256>>>(cb[1]);
    k_stats<<<256, 256>>>(1);
    k_bnp<<<1, 32>>>(1, gg[1], bt[1]);

    // layer 2
    k_xw<32, true><<<(NN + 7) / 8, 256>>>(nullptr, cW[2]);
    k_gather<<<(NN * 8 + 255) / 256, 256>>>(cb[2]);
    k_stats<<<256, 256>>>(2);
    k_bnp<<<1, 32>>>(2, gg[2], bt[2]);

    // final BN apply -> FC input
    k_bnapply<<<(NN * 32 + 255) / 256, 256>>>();

    // FC stack
    k_fc0<<<2048, 128>>>(fW0);
    k_fctail<<<1, 128>>>(fb0, fW1, fb1, fW2, fb2, fW3, fb3, out);
    (void)in_sizes; (void)n_in; (void)out_size;
}

// round 3
// speedup vs baseline: 1.1758x; 1.1758x over previous
#include <cuda_runtime.h>

#define NN   50000
#define HH   128
#define EE   1600000
#define EPSB 1e-5f
#define NB   196          // ceil(50000/256) scan blocks

// -------- static device scratch --------
__device__ int   g_row[EE];
__device__ int   g_col[EE];
__device__ int2  g_edge[EE];    // CSR: (src, weight-as-int-bits)
__device__ int   g_deg[NN];
__device__ float g_dinv[NN];
__device__ int   g_ptr[NN + 1];
__device__ int   g_pos[NN];
__device__ int   g_part[NB];
__device__ float g_xw[NN * 32];
__device__ float g_y [NN * 32];   // post-lrelu layer output
__device__ float g_ssum[3 * 32];
__device__ float g_ssq [3 * 32];
__device__ int   g_cnt[3];
__device__ float g_bnA[32];
__device__ float g_bnB[32];
__device__ float g_fc0[128];
__device__ int   g_is64;

static __device__ __forceinline__ float lrelu(float v) {
    return v > 0.f ? v : 0.1f * v;
}

// -------- init: zero accumulators + dtype detect --------
__global__ void k_init(const unsigned int* w) {
    int i = blockIdx.x * blockDim.x + threadIdx.x;
    if (i < NN) g_deg[i] = 0;
    if (i < 3 * 32) { g_ssum[i] = 0.f; g_ssq[i] = 0.f; }
    if (i < 128) g_fc0[i] = 0.f;
    if (i < 3) g_cnt[i] = 0;
    if (i == 0) {
        int nz = 0;
        for (int t = 0; t < 64; t++) nz += (w[2 * t + 1] != 0u);
        g_is64 = (nz == 0) ? 1 : 0;
    }
}

// -------- decode edges + degree histogram --------
__global__ void k_edges(const void* ei) {
    int e = blockIdx.x * blockDim.x + threadIdx.x;
    if (e >= EE) return;
    int r, c;
    if (g_is64) {
        const long long* p = (const long long*)ei;
        r = (int)p[e]; c = (int)p[EE + e];
    } else {
        const int* p = (const int*)ei;
        r = p[e]; c = p[EE + e];
    }
    g_row[e] = r; g_col[e] = c;
    atomicAdd(&g_deg[c], 1);
}

// -------- scan phase 1: per-block partial sums + dinv --------
__global__ __launch_bounds__(256) void k_scan1() {
    __shared__ int sh[256];
    int i = blockIdx.x * 256 + threadIdx.x;
    int v = (i < NN) ? g_deg[i] : 0;
    if (i < NN) g_dinv[i] = rsqrtf((float)v + 2.0f);
    sh[threadIdx.x] = v;
    __syncthreads();
#pragma unroll
    for (int off = 128; off > 0; off >>= 1) {
        if (threadIdx.x < off) sh[threadIdx.x] += sh[threadIdx.x + off];
        __syncthreads();
    }
    if (threadIdx.x == 0) g_part[blockIdx.x] = sh[0];
}

// -------- scan phase 2: exclusive scan of NB partials (1 block) --------
__global__ __launch_bounds__(256) void k_scan2() {
    __shared__ int sh[256];
    int t = threadIdx.x;
    int v = (t < NB) ? g_part[t] : 0;
    sh[t] = v;
    __syncthreads();
#pragma unroll
    for (int off = 1; off < 256; off <<= 1) {
        int u = (t >= off) ? sh[t - off] : 0;
        __syncthreads();
        sh[t] += u;
        __syncthreads();
    }
    if (t < NB) g_part[t] = sh[t] - v;   // exclusive
    if (t == 0) g_ptr[NN] = EE;
}

// -------- scan phase 3: local exclusive scan + offsets --------
__global__ __launch_bounds__(256) void k_scan3() {
    __shared__ int sh[256];
    int t = threadIdx.x;
    int i = blockIdx.x * 256 + t;
    int v = (i < NN) ? g_deg[i] : 0;
    sh[t] = v;
    __syncthreads();
#pragma unroll
    for (int off = 1; off < 256; off <<= 1) {
        int u = (t >= off) ? sh[t - off] : 0;
        __syncthreads();
        sh[t] += u;
        __syncthreads();
    }
    if (i < NN) {
        int excl = g_part[blockIdx.x] + sh[t] - v;
        g_ptr[i] = excl;
        g_pos[i] = excl;
    }
}

// -------- CSR placement: packed (src, weight) --------
__global__ void k_place() {
    int e = blockIdx.x * blockDim.x + threadIdx.x;
    if (e >= EE) return;
    int r = g_row[e], c = g_col[e];
    int slot = atomicAdd(&g_pos[c], 1);
    float w = g_dinv[r] * g_dinv[c];
    g_edge[slot] = make_int2(r, __float_as_int(w));
}

// -------- xw = (BN(x)) @ W ; one warp per node --------
template<int CIN, bool BN>
__global__ __launch_bounds__(256) void k_xw(const float* __restrict__ x,
                                            const float* __restrict__ W) {
    __shared__ float sW[CIN * 32];
    for (int t = threadIdx.x; t < CIN * 32; t += 256) sW[t] = W[t];
    __syncthreads();
    int warp = threadIdx.x >> 5, lane = threadIdx.x & 31;
    int node = blockIdx.x * 8 + warp;
    if (node >= NN) return;
    const float* xr = BN ? (g_y + (size_t)node * CIN) : (x + (size_t)node * CIN);
    float acc = 0.f;
    if (CIN == 32) {
        float v = xr[lane];
        if (BN) v = v * g_bnA[lane] + g_bnB[lane];
#pragma unroll
        for (int k = 0; k < 32; k++)
            acc += __shfl_sync(0xffffffffu, v, k) * sW[k * 32 + lane];
    } else {
        float v0 = xr[lane], v1 = xr[lane + 32], v2 = xr[lane + 64], v3 = xr[lane + 96];
#pragma unroll
        for (int k = 0; k < 32; k++)
            acc += __shfl_sync(0xffffffffu, v0, k) * sW[k * 32 + lane];
#pragma unroll
        for (int k = 0; k < 32; k++)
            acc += __shfl_sync(0xffffffffu, v1, k) * sW[(k + 32) * 32 + lane];
#pragma unroll
        for (int k = 0; k < 32; k++)
            acc += __shfl_sync(0xffffffffu, v2, k) * sW[(k + 64) * 32 + lane];
#pragma unroll
        for (int k = 0; k < 32; k++)
            acc += __shfl_sync(0xffffffffu, v3, k) * sW[(k + 96) * 32 + lane];
    }
    g_xw[node * 32 + lane] = acc;
}

// -------- gather aggregation + self loop + bias + lrelu --------
__global__ __launch_bounds__(256) void k_gather(const float* __restrict__ b) {
    int tid = blockIdx.x * blockDim.x + threadIdx.x;
    int node = tid >> 3, q = tid & 7;
    if (node >= NN) return;
    const float4* xw4 = (const float4*)g_xw;
    float di = g_dinv[node];
    float sw = 2.f * di * di;
    float4 self = xw4[node * 8 + q];
    float4 acc;
    acc.x = self.x * sw + b[q * 4 + 0];
    acc.y = self.y * sw + b[q * 4 + 1];
    acc.z = self.z * sw + b[q * 4 + 2];
    acc.w = self.w * sw + b[q * 4 + 3];
    int s = g_ptr[node], e = g_ptr[node + 1];
    int i = s;
    for (; i + 3 < e; i += 4) {
        int2 e0 = __ldg(&g_edge[i]);
        int2 e1 = __ldg(&g_edge[i + 1]);
        int2 e2 = __ldg(&g_edge[i + 2]);
        int2 e3 = __ldg(&g_edge[i + 3]);
        float4 v0 = xw4[e0.x * 8 + q];
        float4 v1 = xw4[e1.x * 8 + q];
        float4 v2 = xw4[e2.x * 8 + q];
        float4 v3 = xw4[e3.x * 8 + q];
        float w0 = __int_as_float(e0.y), w1 = __int_as_float(e1.y);
        float w2 = __int_as_float(e2.y), w3 = __int_as_float(e3.y);
        acc.x += w0 * v0.x + w1 * v1.x + w2 * v2.x + w3 * v3.x;
        acc.y += w0 * v0.y + w1 * v1.y + w2 * v2.y + w3 * v3.y;
        acc.z += w0 * v0.z + w1 * v1.z + w2 * v2.z + w3 * v3.z;
        acc.w += w0 * v0.w + w1 * v1.w + w2 * v2.w + w3 * v3.w;
    }
    for (; i < e; i++) {
        int2 e0 = __ldg(&g_edge[i]);
        float w0 = __int_as_float(e0.y);
        float4 v0 = xw4[e0.x * 8 + q];
        acc.x += w0 * v0.x; acc.y += w0 * v0.y;
        acc.z += w0 * v0.z; acc.w += w0 * v0.w;
    }
    acc.x = lrelu(acc.x); acc.y = lrelu(acc.y);
    acc.z = lrelu(acc.z); acc.w = lrelu(acc.w);
    ((float4*)g_y)[node * 8 + q] = acc;
}

// -------- BN stats + fold (last block computes bnA/bnB) --------
__global__ __launch_bounds__(256) void k_stats(int layer,
                                               const float* __restrict__ g,
                                               const float* __restrict__ bt) {
    int c = threadIdx.x & 31;
    int r = threadIdx.x >> 5;
    float s = 0.f, s2 = 0.f;
    for (int i = blockIdx.x * 8 + r; i < NN; i += gridDim.x * 8) {
        float v = g_y[i * 32 + c];
        s += v; s2 += v * v;
    }
    __shared__ float sh[256], sh2[256];
    __shared__ bool last;
    sh[threadIdx.x] = s; sh2[threadIdx.x] = s2;
    __syncthreads();
    if (r == 0) {
#pragma unroll
        for (int k = 1; k < 8; k++) { s += sh[k * 32 + c]; s2 += sh2[k * 32 + c]; }
        atomicAdd(&g_ssum[layer * 32 + c], s);
        atomicAdd(&g_ssq [layer * 32 + c], s2);
    }
    __threadfence();
    __syncthreads();
    if (threadIdx.x == 0) {
        int t = atomicAdd(&g_cnt[layer], 1);
        last = (t == (int)gridDim.x - 1);
    }
    __syncthreads();
    if (last && threadIdx.x < 32) {
        float sum = atomicAdd(&g_ssum[layer * 32 + threadIdx.x], 0.f);
        float sq  = atomicAdd(&g_ssq [layer * 32 + threadIdx.x], 0.f);
        float mean = sum / (float)NN;
        float var  = sq / (float)NN - mean * mean;
        float a = g[threadIdx.x] * rsqrtf(var + EPSB);
        g_bnA[threadIdx.x] = a;
        g_bnB[threadIdx.x] = bt[threadIdx.x] - mean * a;
    }
}

// -------- FC0: [1, 1.6M] x [1.6M, 128], BN affine folded into x --------
__global__ __launch_bounds__(128) void k_fc0(const float* __restrict__ W0) {
    const int total = NN * 32;
    int per = ((total + gridDim.x - 1) / gridDim.x + 127) & ~127;
    int k0 = blockIdx.x * per;
    if (k0 >= total) return;
    int k1 = min(k0 + per, total);
    int j = threadIdx.x;
    float bnA = g_bnA[j & 31], bnB = g_bnB[j & 31];
    __shared__ float sx[128];
    float acc = 0.f;
    for (int kb = k0; kb < k1; kb += 128) {
        int kk = kb + j;
        sx[j] = (kk < k1) ? (g_y[kk] * bnA + bnB) : 0.f;
        __syncthreads();
        int lim = min(128, k1 - kb);
#pragma unroll 8
        for (int t = 0; t < lim; t++)
            acc += sx[t] * W0[(size_t)(kb + t) * 128 + j];
        __syncthreads();
    }
    atomicAdd(&g_fc0[j], acc);
}

// -------- FC tail: bias+lrelu, 128->64->32->1 --------
__global__ void k_fctail(const float* __restrict__ fb0,
                         const float* __restrict__ fW1, const float* __restrict__ fb1,
                         const float* __restrict__ fW2, const float* __restrict__ fb2,
                         const float* __restrict__ fW3, const float* __restrict__ fb3,
                         float* __restrict__ out) {
    __shared__ float h1[128], h2[64], h3[32];
    int t = threadIdx.x;
    h1[t] = lrelu(g_fc0[t] + fb0[t]);
    __syncthreads();
    if (t < 64) {
        float a = fb1[t];
#pragma unroll 8
        for (int k = 0; k < 128; k++) a += h1[k] * fW1[k * 64 + t];
        h2[t] = lrelu(a);
    }
    __syncthreads();
    if (t < 32) {
        float a = fb2[t];
#pragma unroll 8
        for (int k = 0; k < 64; k++) a += h2[k] * fW2[k * 32 + t];
        h3[t] = lrelu(a);
    }
    __syncthreads();
    if (t == 0) {
        float a = fb3[0];
#pragma unroll
        for (int k = 0; k < 32; k++) a += h3[k] * fW3[k];
        out[0] = a;
    }
}

extern "C" void kernel_launch(void* const* d_in, const int* in_sizes, int n_in,
                              void* d_out, int out_size) {
    const void*  ei   = d_in[0];
    const float* emb  = (const float*)d_in[1];
    const float* cW[3] = {(const float*)d_in[2], (const float*)d_in[6], (const float*)d_in[10]};
    const float* cb[3] = {(const float*)d_in[3], (const float*)d_in[7], (const float*)d_in[11]};
    const float* gg[3] = {(const float*)d_in[4], (const float*)d_in[8], (const float*)d_in[12]};
    const float* bt[3] = {(const float*)d_in[5], (const float*)d_in[9], (const float*)d_in[13]};
    const float* fW0 = (const float*)d_in[14];
    const float* fb0 = (const float*)d_in[15];
    const float* fW1 = (const float*)d_in[16];
    const float* fb1 = (const float*)d_in[17];
    const float* fW2 = (const float*)d_in[18];
    const float* fb2 = (const float*)d_in[19];
    const float* fW3 = (const float*)d_in[20];
    const float* fb3 = (const float*)d_in[21];
    float* out = (float*)d_out;

    k_init<<<(NN + 255) / 256, 256>>>((const unsigned int*)ei);
    k_edges<<<(EE + 255) / 256, 256>>>(ei);
    k_scan1<<<NB, 256>>>();
    k_scan2<<<1, 256>>>();
    k_scan3<<<NB, 256>>>();
    k_place<<<(EE + 255) / 256, 256>>>();

    // layer 0 (CIN=128, no BN on input)
    k_xw<128, false><<<(NN + 7) / 8, 256>>>(emb, cW[0]);
    k_gather<<<(NN * 8 + 255) / 256, 256>>>(cb[0]);
    k_stats<<<256, 256>>>(0, gg[0], bt[0]);

    // layer 1 (CIN=32, BN folded into xw input, reads g_y device-side)
    k_xw<32, true><<<(NN + 7) / 8, 256>>>(nullptr, cW[1]);
    k_gather<<<(NN * 8 + 255) / 256, 256>>>(cb[1]);
    k_stats<<<256, 256>>>(1, gg[1], bt[1]);

    // layer 2
    k_xw<32, true><<<(NN + 7) / 8, 256>>>(nullptr, cW[2]);
    k_gather<<<(NN * 8 + 255) / 256, 256>>>(cb[2]);
    k_stats<<<256, 256>>>(2, gg[2], bt[2]);

    // FC stack (BN of layer 2 folded into FC0's x load)
    k_fc0<<<2048, 128>>>(fW0);
    k_fctail<<<1, 128>>>(fb0, fW1, fb1, fW2, fb2, fW3, fb3, out);
    (void)in_sizes; (void)n_in; (void)out_size;
}